// round 4
// baseline (speedup 1.0000x reference)
#include <cuda_runtime.h>
#include <cuda_bf16.h>

#define NLON 1440
#define NLAT 721
#define NB   8

// Scratch: x transposed to [lat][lon][batch] so the 8 batch values of one
// grid node are a single 32-byte sector. 721*1440*8*4B = 33.2 MB.
__device__ float g_xt[(size_t)NLAT * NLON * NB];

__global__ void __launch_bounds__(256) transpose_kernel(const float* __restrict__ x) {
    int ji = blockIdx.x * blockDim.x + threadIdx.x;
    if (ji >= NLAT * NLON) return;
    float v[NB];
#pragma unroll
    for (int b = 0; b < NB; b++)
        v[b] = __ldg(x + (size_t)b * (NLAT * NLON) + ji);
    float4* dst = reinterpret_cast<float4*>(g_xt + (size_t)ji * NB);
    dst[0] = make_float4(v[0], v[1], v[2], v[3]);
    dst[1] = make_float4(v[4], v[5], v[6], v[7]);
}

__global__ void __launch_bounds__(256) interp_kernel(const float2* __restrict__ xi,
                                                     float* __restrict__ out,
                                                     int N) {
    int n = blockIdx.x * blockDim.x + threadIdx.x;
    if (n >= N) return;

    float2 q = __ldg(xi + n);
    float lon = q.x;
    float lat = q.y;

    // Uniform grids with exact spacing 0.25: index = floor(coord * 4).
    float fi = lon * 4.0f;                 // exact (mul by power of 2)
    int i = (int)floorf(fi);
    i = min(max(i, 0), NLON - 1);
    float wlon = fi - (float)i;            // == (lon - 0.25*i) * 4 to 1 ulp

    float fj = (lat + 90.0f) * 4.0f;
    int j = (int)floorf(fj);
    j = min(max(j, 0), NLAT - 2);
    float latg = fmaf(0.25f, (float)j, -90.0f);  // exact grid value
    float wlat = (lat - latg) * 4.0f;

    int ip1 = (i + 1 == NLON) ? 0 : i + 1; // periodic wrap in longitude

    const float4* p00 = reinterpret_cast<const float4*>(g_xt + ((size_t)j * NLON + i) * NB);
    const float4* p10 = reinterpret_cast<const float4*>(g_xt + ((size_t)j * NLON + ip1) * NB);
    const float4* p01 = reinterpret_cast<const float4*>(g_xt + ((size_t)(j + 1) * NLON + i) * NB);
    const float4* p11 = reinterpret_cast<const float4*>(g_xt + ((size_t)(j + 1) * NLON + ip1) * NB);

    float4 a00 = __ldg(p00);     float4 b00 = __ldg(p00 + 1);
    float4 a10 = __ldg(p10);     float4 b10 = __ldg(p10 + 1);
    float4 a01 = __ldg(p01);     float4 b01 = __ldg(p01 + 1);
    float4 a11 = __ldg(p11);     float4 b11 = __ldg(p11 + 1);

    float v00[NB] = {a00.x, a00.y, a00.z, a00.w, b00.x, b00.y, b00.z, b00.w};
    float v10[NB] = {a10.x, a10.y, a10.z, a10.w, b10.x, b10.y, b10.z, b10.w};
    float v01[NB] = {a01.x, a01.y, a01.z, a01.w, b01.x, b01.y, b01.z, b01.w};
    float v11[NB] = {a11.x, a11.y, a11.z, a11.w, b11.x, b11.y, b11.z, b11.w};

    float r[NB];
#pragma unroll
    for (int b = 0; b < NB; b++) {
        float top = fmaf(wlon, v10[b] - v00[b], v00[b]);
        float bot = fmaf(wlon, v11[b] - v01[b], v01[b]);
        r[b] = fmaf(wlat, bot - top, top);
    }

    float4* o = reinterpret_cast<float4*>(out + (size_t)n * NB);
    o[0] = make_float4(r[0], r[1], r[2], r[3]);
    o[1] = make_float4(r[4], r[5], r[6], r[7]);
}

extern "C" void kernel_launch(void* const* d_in, const int* in_sizes, int n_in,
                              void* d_out, int out_size) {
    const float*  x  = (const float*)d_in[0];   // [8, 721, 1440]
    const float2* xi = (const float2*)d_in[3];  // [N, 2]
    float* out = (float*)d_out;                 // [N, 8]
    int N = in_sizes[3] / 2;

    const int T = 256;
    int grid_t = (NLAT * NLON + T - 1) / T;
    transpose_kernel<<<grid_t, T>>>(x);

    int grid_i = (N + T - 1) / T;
    interp_kernel<<<grid_i, T>>>(xi, out, N);
}